// round 1
// baseline (speedup 1.0000x reference)
#include <cuda_runtime.h>
#include <math.h>
#include <stdint.h>

#define S_LEN 2048
#define HID   256
#define BN    16
#define M_ROWS (BN * S_LEN)   // 32768

// Scratch (device globals: no allocation allowed in kernel_launch)
__device__ float  g_Q[(size_t)M_ROWS * HID];
__device__ float  g_K[(size_t)M_ROWS * HID];
__device__ float  g_V[(size_t)M_ROWS * HID];
__device__ float4 g_tab[S_LEN * 128];   // {sin, cos, scale, 1/scale} per (pos, halfdim)

// ---------------------------------------------------------------------------
// xpos table: sin/cos/scale per (position s, half-dim i)
// ---------------------------------------------------------------------------
__global__ void tab_kernel() {
    int idx = blockIdx.x * 256 + threadIdx.x;
    if (idx >= S_LEN * 128) return;
    int s = idx >> 7;
    int i = idx & 127;
    // inv_freq = 1 / 10000^(i/128), computed in double then rounded (matches fp32 ref to ulps)
    float inv_freq = (float)(1.0 / pow(10000.0, (double)i / 128.0));
    float theta = (float)s * inv_freq;
    float sn, cs;
    sincosf(theta, &sn, &cs);
    float base  = ((float)(2 * i) + 102.4f) / 358.4f;   // (2i + 0.4*H)/(1.4*H)
    float scale = (float)pow((double)base, (double)s / 512.0);
    g_tab[idx] = make_float4(sn, cs, scale, 1.0f / scale);
}

// ---------------------------------------------------------------------------
// Fused QKV projection + xpos epilogue.
// grid: (HID/64, M_ROWS/64, 3)  z: 0=Q (xpos), 1=K (xpos downscale), 2=V
// block: 16x16, each thread computes a 4x4 micro-tile.
// ---------------------------------------------------------------------------
__global__ void proj_kernel(const float* __restrict__ X,
                            const float* __restrict__ Wq,
                            const float* __restrict__ Wk,
                            const float* __restrict__ Wv) {
    int mode = blockIdx.z;
    const float* W = (mode == 0) ? Wq : (mode == 1) ? Wk : Wv;
    float* outp = (mode == 0) ? g_Q : (mode == 1) ? g_K : g_V;

    int row0 = blockIdx.y * 64;
    int col0 = blockIdx.x * 64;

    __shared__ float As[64][33];   // [m][k], padded
    __shared__ float Bs[32][64];   // [k][n]

    int tx = threadIdx.x, ty = threadIdx.y;
    int tid = ty * 16 + tx;

    float acc[4][4];
#pragma unroll
    for (int i = 0; i < 4; i++)
#pragma unroll
        for (int j = 0; j < 4; j++) acc[i][j] = 0.f;

    int kk = tid & 31;
    int rbase = tid >> 5;          // 0..7
    int nn = tid & 63;
    int kb = tid >> 6;             // 0..3

    for (int k0 = 0; k0 < HID; k0 += 32) {
#pragma unroll
        for (int i = 0; i < 8; i++) {
            int r = rbase + i * 8;
            As[r][kk] = X[(size_t)(row0 + r) * HID + k0 + kk];
        }
#pragma unroll
        for (int i = 0; i < 8; i++) {
            int k = kb + i * 4;
            Bs[k][nn] = W[(size_t)(k0 + k) * HID + col0 + nn];
        }
        __syncthreads();
#pragma unroll
        for (int k2 = 0; k2 < 32; k2++) {
            float a0 = As[ty * 4 + 0][k2];
            float a1 = As[ty * 4 + 1][k2];
            float a2 = As[ty * 4 + 2][k2];
            float a3 = As[ty * 4 + 3][k2];
            float4 b = ((const float4*)&Bs[k2][0])[tx];
            acc[0][0] += a0 * b.x; acc[0][1] += a0 * b.y; acc[0][2] += a0 * b.z; acc[0][3] += a0 * b.w;
            acc[1][0] += a1 * b.x; acc[1][1] += a1 * b.y; acc[1][2] += a1 * b.z; acc[1][3] += a1 * b.w;
            acc[2][0] += a2 * b.x; acc[2][1] += a2 * b.y; acc[2][2] += a2 * b.z; acc[2][3] += a2 * b.w;
            acc[3][0] += a3 * b.x; acc[3][1] += a3 * b.y; acc[3][2] += a3 * b.z; acc[3][3] += a3 * b.w;
        }
        __syncthreads();
    }

    int col = col0 + tx * 4;
#pragma unroll
    for (int i = 0; i < 4; i++) {
        int gr = row0 + ty * 4 + i;
        float4 r;
        if (mode == 2) {
            r = make_float4(acc[i][0], acc[i][1], acc[i][2], acc[i][3]);
        } else {
            int s = gr & (S_LEN - 1);
            float4 t0 = g_tab[s * 128 + (col >> 1)];
            float4 t1 = g_tab[s * 128 + (col >> 1) + 1];
            float sc0 = (mode == 0) ? t0.z : t0.w;
            float sc1 = (mode == 0) ? t1.z : t1.w;
            float sn0 = t0.x * sc0, cs0 = t0.y * sc0;
            float sn1 = t1.x * sc1, cs1 = t1.y * sc1;
            r.x = acc[i][0] * cs0 - acc[i][1] * sn0;
            r.y = acc[i][1] * cs0 + acc[i][0] * sn0;
            r.z = acc[i][2] * cs1 - acc[i][3] * sn1;
            r.w = acc[i][3] * cs1 + acc[i][2] * sn1;
        }
        ((float4*)(outp + (size_t)gr * HID))[col >> 2] = r;
    }
}

// ---------------------------------------------------------------------------
// Flash-style retention attention.
// grid: (S/32 q-tiles, BN). block 256 threads. 2 CTAs/SM (100 KB dyn smem).
// Decay: gamma^(i-j) = exp2((i-j)*log2(gamma)), causal-masked.
// ---------------------------------------------------------------------------
#define L2G  (-0.045803586f)   // log2(0.96875)
#define GAM  (0.96875f)
#define IGAM (1.0322580645161290f)

__global__ void attn_kernel(float* __restrict__ out) {
    extern __shared__ float sm[];
    float* Qs = sm;                    // 32*256
    float* Ks = Qs + 32 * HID;         // 32*256
    float* Vs = Ks + 32 * HID;         // 32*256
    float* Ps = Vs + 32 * HID;         // 32*32

    int qt = gridDim.x - 1 - blockIdx.x;   // heavy blocks launch first
    int bn = blockIdx.y;
    int t = threadIdx.x;
    int q0 = qt * 32;

    // load Q tile
    {
        const float4* Qg = (const float4*)(g_Q + ((size_t)bn * S_LEN + q0) * HID);
        float4* Qs4 = (float4*)Qs;
#pragma unroll
        for (int i = 0; i < 8; i++) Qs4[t + i * 256] = Qg[t + i * 256];
    }

    int r0  = (t >> 4) * 2;        // S rows (2)
    int c0  = (t & 15) * 2;        // S cols (2)
    int c0p = (t & 15) * 16;       // PV cols (16)

    float o[2][16];
#pragma unroll
    for (int i = 0; i < 2; i++)
#pragma unroll
        for (int j = 0; j < 16; j++) o[i][j] = 0.f;

    const float4* Q4 = (const float4*)Qs;
    const float4* K4 = (const float4*)Ks;
    const float4* V4 = (const float4*)Vs;

    for (int kt = 0; kt <= qt; kt++) {
        int j0 = kt * 32;
        __syncthreads();   // prior PV reads done (and Q tile visible on first iter)
        {
            const float4* Kg = (const float4*)(g_K + ((size_t)bn * S_LEN + j0) * HID);
            const float4* Vg = (const float4*)(g_V + ((size_t)bn * S_LEN + j0) * HID);
            float4* Ks4 = (float4*)Ks;
            float4* Vs4 = (float4*)Vs;
#pragma unroll
            for (int i = 0; i < 8; i++) {
                Ks4[t + i * 256] = Kg[t + i * 256];
                Vs4[t + i * 256] = Vg[t + i * 256];
            }
        }
        __syncthreads();

        // --- S = Q K^T (2x2 micro-tile over k=256) ---
        float s00 = 0.f, s01 = 0.f, s10 = 0.f, s11 = 0.f;
#pragma unroll 8
        for (int k4 = 0; k4 < 64; k4++) {
            float4 qa = Q4[(r0 + 0) * 64 + k4];
            float4 qb = Q4[(r0 + 1) * 64 + k4];
            float4 ka = K4[(c0 + 0) * 64 + k4];
            float4 kb = K4[(c0 + 1) * 64 + k4];
            s00 += qa.x * ka.x + qa.y * ka.y + qa.z * ka.z + qa.w * ka.w;
            s01 += qa.x * kb.x + qa.y * kb.y + qa.z * kb.z + qa.w * kb.w;
            s10 += qb.x * ka.x + qb.y * ka.y + qb.z * ka.z + qb.w * ka.w;
            s11 += qb.x * kb.x + qb.y * kb.y + qb.z * kb.z + qb.w * kb.w;
        }

        // --- decay + causal mask ---
        int d00 = (q0 + r0) - (j0 + c0);
        float e00 = exp2f((float)d00 * L2G);
        Ps[(r0 + 0) * 32 + c0 + 0] = (d00 >= 0) ? s00 * e00 : 0.f;
        Ps[(r0 + 0) * 32 + c0 + 1] = (d00 >= 1) ? s01 * e00 * IGAM : 0.f;
        Ps[(r0 + 1) * 32 + c0 + 0] = (d00 >= -1) ? s10 * e00 * GAM : 0.f;
        Ps[(r0 + 1) * 32 + c0 + 1] = (d00 >= 0) ? s11 * e00 : 0.f;

        __syncthreads();

        // --- O += P V (2 rows x 16 cols per thread) ---
#pragma unroll 8
        for (int j = 0; j < 32; j++) {
            float p0 = Ps[(r0 + 0) * 32 + j];
            float p1 = Ps[(r0 + 1) * 32 + j];
#pragma unroll
            for (int q = 0; q < 4; q++) {
                float4 v = V4[j * 64 + (c0p >> 2) + q];
                o[0][q * 4 + 0] += p0 * v.x; o[0][q * 4 + 1] += p0 * v.y;
                o[0][q * 4 + 2] += p0 * v.z; o[0][q * 4 + 3] += p0 * v.w;
                o[1][q * 4 + 0] += p1 * v.x; o[1][q * 4 + 1] += p1 * v.y;
                o[1][q * 4 + 2] += p1 * v.z; o[1][q * 4 + 3] += p1 * v.w;
            }
        }
    }

    // write output
    float4* Og = (float4*)(out + ((size_t)bn * S_LEN + q0) * HID);
#pragma unroll
    for (int i = 0; i < 2; i++) {
        int row = r0 + i;
#pragma unroll
        for (int q = 0; q < 4; q++) {
            float4 v = make_float4(o[i][q * 4 + 0], o[i][q * 4 + 1],
                                   o[i][q * 4 + 2], o[i][q * 4 + 3]);
            Og[row * 64 + (c0p >> 2) + q] = v;
        }
    }
}

// ---------------------------------------------------------------------------
extern "C" void kernel_launch(void* const* d_in, const int* in_sizes, int n_in,
                              void* d_out, int out_size) {
    const float* X  = (const float*)d_in[0];
    const float* Wq = (const float*)d_in[1];
    const float* Wk = (const float*)d_in[2];
    const float* Wv = (const float*)d_in[3];
    float* out = (float*)d_out;

    // 1) xpos table
    tab_kernel<<<(S_LEN * 128 + 255) / 256, 256>>>();

    // 2) fused QKV projection + xpos
    dim3 pgrid(HID / 64, M_ROWS / 64, 3);
    proj_kernel<<<pgrid, dim3(16, 16)>>>(X, Wq, Wk, Wv);

    // 3) retention attention
    int smem = (32 * HID * 3 + 32 * 32) * (int)sizeof(float);   // 102400 B
    cudaFuncSetAttribute(attn_kernel, cudaFuncAttributeMaxDynamicSharedMemorySize, smem);
    attn_kernel<<<dim3(S_LEN / 32, BN), 256, smem>>>(out);
}

// round 2
// speedup vs baseline: 3.6695x; 3.6695x over previous
#include <cuda_runtime.h>
#include <math.h>
#include <stdint.h>

#define S_LEN 2048
#define HID   256
#define BN    16
#define M_ROWS (BN * S_LEN)   // 32768

// Scratch (device globals: no allocation allowed in kernel_launch)
__device__ float  g_Q[(size_t)M_ROWS * HID];
__device__ float  g_K[(size_t)M_ROWS * HID];
__device__ float  g_V[(size_t)M_ROWS * HID];
__device__ float4 g_tab[S_LEN * 128];   // {sin, cos, scale, 1/scale} per (pos, halfdim)

// ---------------------------------------------------------------------------
// xpos table: sin/cos/scale per (position s, half-dim i)
// ---------------------------------------------------------------------------
__global__ void tab_kernel() {
    int idx = blockIdx.x * 256 + threadIdx.x;
    if (idx >= S_LEN * 128) return;
    int s = idx >> 7;
    int i = idx & 127;
    // inv_freq = 10000^(-i/128) = exp2(-i * log2(10000)/128), double (phase-sensitive)
    float inv_freq = (float)exp2(-(double)i * (13.287712379549449 / 128.0));
    float theta = (float)s * inv_freq;
    float sn, cs;
    sincosf(theta, &sn, &cs);
    float base  = ((float)(2 * i) + 102.4f) / 358.4f;   // (2i + 0.4*H)/(1.4*H)
    float scale = exp2f(log2f(base) * ((float)s * (1.0f / 512.0f)));
    g_tab[idx] = make_float4(sn, cs, scale, 1.0f / scale);
}

// ---------------------------------------------------------------------------
// Fused QKV projection + xpos epilogue.
// grid: (HID/64, M_ROWS/64, 3)  z: 0=Q (xpos), 1=K (xpos downscale), 2=V
// block: 16x16, each thread computes a 4x4 micro-tile.
// ---------------------------------------------------------------------------
__global__ void __launch_bounds__(256) proj_kernel(
                            const float* __restrict__ X,
                            const float* __restrict__ Wq,
                            const float* __restrict__ Wk,
                            const float* __restrict__ Wv) {
    int mode = blockIdx.z;
    const float* W = (mode == 0) ? Wq : (mode == 1) ? Wk : Wv;
    float* outp = (mode == 0) ? g_Q : (mode == 1) ? g_K : g_V;

    int row0 = blockIdx.y * 64;
    int col0 = blockIdx.x * 64;

    __shared__ float As[64][33];   // [m][k], padded
    __shared__ float Bs[32][64];   // [k][n]

    int tx = threadIdx.x, ty = threadIdx.y;
    int tid = ty * 16 + tx;

    float acc[4][4];
#pragma unroll
    for (int i = 0; i < 4; i++)
#pragma unroll
        for (int j = 0; j < 4; j++) acc[i][j] = 0.f;

    int kk = tid & 31;
    int rbase = tid >> 5;          // 0..7
    int nn = tid & 63;
    int kb = tid >> 6;             // 0..3

    for (int k0 = 0; k0 < HID; k0 += 32) {
#pragma unroll
        for (int i = 0; i < 8; i++) {
            int r = rbase + i * 8;
            As[r][kk] = X[(size_t)(row0 + r) * HID + k0 + kk];
        }
#pragma unroll
        for (int i = 0; i < 8; i++) {
            int k = kb + i * 4;
            Bs[k][nn] = W[(size_t)(k0 + k) * HID + col0 + nn];
        }
        __syncthreads();
#pragma unroll
        for (int k2 = 0; k2 < 32; k2++) {
            float a0 = As[ty * 4 + 0][k2];
            float a1 = As[ty * 4 + 1][k2];
            float a2 = As[ty * 4 + 2][k2];
            float a3 = As[ty * 4 + 3][k2];
            float4 b = ((const float4*)&Bs[k2][0])[tx];
            acc[0][0] += a0 * b.x; acc[0][1] += a0 * b.y; acc[0][2] += a0 * b.z; acc[0][3] += a0 * b.w;
            acc[1][0] += a1 * b.x; acc[1][1] += a1 * b.y; acc[1][2] += a1 * b.z; acc[1][3] += a1 * b.w;
            acc[2][0] += a2 * b.x; acc[2][1] += a2 * b.y; acc[2][2] += a2 * b.z; acc[2][3] += a2 * b.w;
            acc[3][0] += a3 * b.x; acc[3][1] += a3 * b.y; acc[3][2] += a3 * b.z; acc[3][3] += a3 * b.w;
        }
        __syncthreads();
    }

    int col = col0 + tx * 4;
#pragma unroll
    for (int i = 0; i < 4; i++) {
        int gr = row0 + ty * 4 + i;
        float4 r;
        if (mode == 2) {
            r = make_float4(acc[i][0], acc[i][1], acc[i][2], acc[i][3]);
        } else {
            int s = gr & (S_LEN - 1);
            float4 t0 = g_tab[s * 128 + (col >> 1)];
            float4 t1 = g_tab[s * 128 + (col >> 1) + 1];
            float sc0 = (mode == 0) ? t0.z : t0.w;
            float sc1 = (mode == 0) ? t1.z : t1.w;
            float sn0 = t0.x * sc0, cs0 = t0.y * sc0;
            float sn1 = t1.x * sc1, cs1 = t1.y * sc1;
            r.x = acc[i][0] * cs0 - acc[i][1] * sn0;
            r.y = acc[i][1] * cs0 + acc[i][0] * sn0;
            r.z = acc[i][2] * cs1 - acc[i][3] * sn1;
            r.w = acc[i][3] * cs1 + acc[i][2] * sn1;
        }
        ((float4*)(outp + (size_t)gr * HID))[col >> 2] = r;
    }
}

// ---------------------------------------------------------------------------
// Flash-style retention attention, bank-conflict-free smem mapping.
// grid: (S/32 q-tiles, BN). block 256 threads. 2 CTAs/SM (~101 KB dyn smem).
// Q/K smem rows padded to 65 float4 (260 floats) so lanes sweep all bank
// groups; micro-tile columns are {c, c+16} (lane-consecutive), PV columns are
// {l, l+16, l+32, l+48} float4 chunks (lane-consecutive within a V row).
// ---------------------------------------------------------------------------
#define L2G  (-0.045803586f)   // log2(0.96875)
#define QK_STR4 65              // padded row stride in float4

__global__ void __launch_bounds__(256, 2) attn_kernel(float* __restrict__ out) {
    extern __shared__ float sm[];
    float4* Qs4 = (float4*)sm;                         // 32 x 65 float4
    float4* Ks4 = Qs4 + 32 * QK_STR4;                  // 32 x 65 float4
    float4* Vs4 = Ks4 + 32 * QK_STR4;                  // 32 x 64 float4
    float*  Ps  = (float*)(Vs4 + 32 * 64);             // 32 x 33 floats

    int qt = gridDim.x - 1 - blockIdx.x;   // heavy blocks launch first
    int bn = blockIdx.y;
    int t  = threadIdx.x;
    int q0 = qt * 32;

    int R = t >> 4;        // S rows {R, R+16}
    int C = t & 15;        // S cols {C, C+16}; PV col chunks {C, C+16, C+32, C+48} (float4)

    // load Q tile (padded rows)
    {
        const float4* Qg = (const float4*)(g_Q + ((size_t)bn * S_LEN + q0) * HID);
#pragma unroll
        for (int i = 0; i < 8; i++) {
            int idx = t + i * 256;
            Qs4[(idx >> 6) * QK_STR4 + (idx & 63)] = Qg[idx];
        }
    }

    float o[2][16];
#pragma unroll
    for (int i = 0; i < 2; i++)
#pragma unroll
        for (int j = 0; j < 16; j++) o[i][j] = 0.f;

    for (int kt = 0; kt <= qt; kt++) {
        int j0 = kt * 32;
        __syncthreads();   // prior PV reads done (and Q tile visible on first iter)
        {
            const float4* Kg = (const float4*)(g_K + ((size_t)bn * S_LEN + j0) * HID);
            const float4* Vg = (const float4*)(g_V + ((size_t)bn * S_LEN + j0) * HID);
#pragma unroll
            for (int i = 0; i < 8; i++) {
                int idx = t + i * 256;
                Ks4[(idx >> 6) * QK_STR4 + (idx & 63)] = Kg[idx];
                Vs4[idx] = Vg[idx];
            }
        }
        __syncthreads();

        // --- S = Q K^T (2x2 micro-tile over k=256) ---
        float s00 = 0.f, s01 = 0.f, s10 = 0.f, s11 = 0.f;
        const float4* qa4 = Qs4 + (R +  0) * QK_STR4;
        const float4* qb4 = Qs4 + (R + 16) * QK_STR4;
        const float4* ka4 = Ks4 + (C +  0) * QK_STR4;
        const float4* kb4 = Ks4 + (C + 16) * QK_STR4;
#pragma unroll 8
        for (int k4 = 0; k4 < 64; k4++) {
            float4 qa = qa4[k4];
            float4 qb = qb4[k4];
            float4 ka = ka4[k4];
            float4 kb = kb4[k4];
            s00 += qa.x * ka.x + qa.y * ka.y + qa.z * ka.z + qa.w * ka.w;
            s01 += qa.x * kb.x + qa.y * kb.y + qa.z * kb.z + qa.w * kb.w;
            s10 += qb.x * ka.x + qb.y * ka.y + qb.z * ka.z + qb.w * ka.w;
            s11 += qb.x * kb.x + qb.y * kb.y + qb.z * kb.z + qb.w * kb.w;
        }

        // --- decay + causal mask ---
        // element diffs: (R,C)=dA, (R,C+16)=dA-16, (R+16,C)=dA+16, (R+16,C+16)=dA
        int dA = (q0 + R) - (j0 + C);
        float eA = exp2f((float)dA        * L2G);
        float eM = exp2f((float)(dA - 16) * L2G);
        float eP = exp2f((float)(dA + 16) * L2G);
        Ps[(R +  0) * 33 + C +  0] = (dA >=   0) ? s00 * eA : 0.f;
        Ps[(R +  0) * 33 + C + 16] = (dA >=  16) ? s01 * eM : 0.f;
        Ps[(R + 16) * 33 + C +  0] = (dA >= -16) ? s10 * eP : 0.f;
        Ps[(R + 16) * 33 + C + 16] = (dA >=   0) ? s11 * eA : 0.f;

        __syncthreads();

        // --- O += P V (2 rows x 16 cols per thread, lane-consecutive chunks) ---
#pragma unroll 8
        for (int j = 0; j < 32; j++) {
            float p0 = Ps[(R +  0) * 33 + j];
            float p1 = Ps[(R + 16) * 33 + j];
            const float4* vr = Vs4 + j * 64;
#pragma unroll
            for (int q = 0; q < 4; q++) {
                float4 v = vr[C + 16 * q];
                o[0][q * 4 + 0] += p0 * v.x; o[0][q * 4 + 1] += p0 * v.y;
                o[0][q * 4 + 2] += p0 * v.z; o[0][q * 4 + 3] += p0 * v.w;
                o[1][q * 4 + 0] += p1 * v.x; o[1][q * 4 + 1] += p1 * v.y;
                o[1][q * 4 + 2] += p1 * v.z; o[1][q * 4 + 3] += p1 * v.w;
            }
        }
    }

    // write output
    float4* Og = (float4*)(out + ((size_t)bn * S_LEN + q0) * HID);
#pragma unroll
    for (int i = 0; i < 2; i++) {
        int row = R + i * 16;
#pragma unroll
        for (int q = 0; q < 4; q++) {
            float4 v = make_float4(o[i][q * 4 + 0], o[i][q * 4 + 1],
                                   o[i][q * 4 + 2], o[i][q * 4 + 3]);
            Og[row * 64 + C + 16 * q] = v;
        }
    }
}

// ---------------------------------------------------------------------------
extern "C" void kernel_launch(void* const* d_in, const int* in_sizes, int n_in,
                              void* d_out, int out_size) {
    const float* X  = (const float*)d_in[0];
    const float* Wq = (const float*)d_in[1];
    const float* Wk = (const float*)d_in[2];
    const float* Wv = (const float*)d_in[3];
    float* out = (float*)d_out;

    // 1) xpos table
    tab_kernel<<<(S_LEN * 128 + 255) / 256, 256>>>();

    // 2) fused QKV projection + xpos
    dim3 pgrid(HID / 64, M_ROWS / 64, 3);
    proj_kernel<<<pgrid, dim3(16, 16)>>>(X, Wq, Wk, Wv);

    // 3) retention attention
    int smem = (32 * QK_STR4 * 4 * 2 + 32 * 64 * 4 + 32 * 33) * (int)sizeof(float);
    cudaFuncSetAttribute(attn_kernel, cudaFuncAttributeMaxDynamicSharedMemorySize, smem);
    attn_kernel<<<dim3(S_LEN / 32, BN), 256, smem>>>(out);
}